// round 2
// baseline (speedup 1.0000x reference)
#include <cuda_runtime.h>
#include <cuda_bf16.h>

#define BB    64      // batch
#define LL    4096    // seq len
#define DD    256     // hidden dim
#define VOCAB 33
#define NT    256     // threads per block
#define NWARP 8

__global__ __launch_bounds__(NT, 1)
void prot_net_fused_kernel(const int* __restrict__ X,
                           const int* __restrict__ vlen,
                           const float* __restrict__ emb,
                           const float* __restrict__ W1,
                           const float* __restrict__ b1,
                           const float* __restrict__ W2,
                           const float* __restrict__ b2,
                           float* __restrict__ out)
{
    __shared__ int   whist[NWARP][VOCAB];
    __shared__ float cnt[VOCAB];
    __shared__ alignas(16) float vecA[DD];     // pooled, then h
    __shared__ alignas(16) float part[4][DD];  // split-K partials (STS.128 target)

    const int b    = blockIdx.x;
    const int tid  = threadIdx.x;
    const int warp = tid >> 5;

    // ---- per-warp histogram of X[b, 0:valid_len[b]) ----
    for (int i = tid; i < NWARP * VOCAB; i += NT)
        (&whist[0][0])[i] = 0;
    __syncthreads();

    const int  vl = vlen[b];
    const int* Xb = X + b * LL;
    #pragma unroll 4
    for (int l = tid; l < LL; l += NT) {
        if (l < vl) {
            int tok = Xb[l];
            atomicAdd(&whist[warp][tok], 1);
        }
    }
    __syncthreads();

    if (tid < VOCAB) {
        int s = 0;
        #pragma unroll
        for (int w = 0; w < NWARP; w++) s += whist[w][tid];
        cnt[tid] = (float)s;
    }
    __syncthreads();

    // ---- pooled[d] = sum_v cnt[v] * emb[v][d] ----
    {
        float acc = 0.0f;
        #pragma unroll
        for (int v = 0; v < VOCAB; v++)
            acc = fmaf(cnt[v], emb[v * DD + tid], acc);
        vecA[tid] = acc;
    }
    __syncthreads();

    const int g    = tid >> 6;   // split-K group: 0..3
    const int lane = tid & 63;   // output float4 index: dims [4*lane, 4*lane+4)

    // ---- layer 1: h = relu(pooled @ W1 + b1), split-K x4, float4 loads ----
    {
        const float4* W1v = (const float4*)W1;
        float4 acc = make_float4(0.f, 0.f, 0.f, 0.f);
        const int k0 = g * 64;
        #pragma unroll 8
        for (int kk = 0; kk < 64; kk++) {
            const int k = k0 + kk;
            const float  s = vecA[k];                  // warp-uniform broadcast
            const float4 w = W1v[k * (DD / 4) + lane]; // coalesced LDG.128
            acc.x = fmaf(s, w.x, acc.x);
            acc.y = fmaf(s, w.y, acc.y);
            acc.z = fmaf(s, w.z, acc.z);
            acc.w = fmaf(s, w.w, acc.w);
        }
        ((float4*)part[g])[lane] = acc;
        __syncthreads();  // all reads of old vecA done; partials visible

        float h = b1[tid] + part[0][tid] + part[1][tid] + part[2][tid] + part[3][tid];
        h = fmaxf(h, 0.0f);
        vecA[tid] = h;    // safe: old vecA fully consumed before the sync above
        __syncthreads();  // new vecA visible; part reads done before reuse
    }

    // ---- layer 2: out = relu(h @ W2 + b2) ----
    {
        const float4* W2v = (const float4*)W2;
        float4 acc = make_float4(0.f, 0.f, 0.f, 0.f);
        const int k0 = g * 64;
        #pragma unroll 8
        for (int kk = 0; kk < 64; kk++) {
            const int k = k0 + kk;
            const float  s = vecA[k];
            const float4 w = W2v[k * (DD / 4) + lane];
            acc.x = fmaf(s, w.x, acc.x);
            acc.y = fmaf(s, w.y, acc.y);
            acc.z = fmaf(s, w.z, acc.z);
            acc.w = fmaf(s, w.w, acc.w);
        }
        ((float4*)part[g])[lane] = acc;
        __syncthreads();

        float o = b2[tid] + part[0][tid] + part[1][tid] + part[2][tid] + part[3][tid];
        out[b * DD + tid] = fmaxf(o, 0.0f);
    }
}

extern "C" void kernel_launch(void* const* d_in, const int* in_sizes, int n_in,
                              void* d_out, int out_size)
{
    const int*   X    = (const int*)d_in[0];
    const int*   vlen = (const int*)d_in[1];
    const float* emb  = (const float*)d_in[2];
    const float* W1   = (const float*)d_in[3];
    const float* b1   = (const float*)d_in[4];
    const float* W2   = (const float*)d_in[5];
    const float* b2   = (const float*)d_in[6];
    float*       out  = (float*)d_out;

    prot_net_fused_kernel<<<BB, NT>>>(X, vlen, emb, W1, b1, W2, b2, out);
}

// round 3
// speedup vs baseline: 1.3070x; 1.3070x over previous
#include <cuda_runtime.h>
#include <cuda_bf16.h>

#define BB    64      // batch
#define LL    4096    // seq len
#define DD    256     // hidden dim
#define VOCAB 33
#define NT    1024    // threads per block
#define NWARP 32
#define KG    16      // split-K groups
#define KPG   16      // k per group

__global__ __launch_bounds__(NT, 1)
void prot_net_fused_kernel(const int* __restrict__ X,
                           const int* __restrict__ vlen,
                           const float* __restrict__ emb,
                           const float* __restrict__ W1,
                           const float* __restrict__ b1,
                           const float* __restrict__ W2,
                           const float* __restrict__ b2,
                           float* __restrict__ out)
{
    __shared__ int   whist[NWARP][VOCAB];              // 4224 B
    __shared__ float cnt[36];                          // padded, [33..35]=0
    __shared__ alignas(16) float vecA[DD];             // pooled, then h
    __shared__ alignas(16) float part[KG][DD];         // 16 KB partials

    const int b    = blockIdx.x;
    const int tid  = threadIdx.x;
    const int warp = tid >> 5;

    // ---- zero per-warp histograms ----
    for (int i = tid; i < NWARP * VOCAB; i += NT)
        (&whist[0][0])[i] = 0;
    __syncthreads();

    // ---- histogram: one int4 of X per thread ----
    const int vl = vlen[b];
    const int l0 = tid * 4;
    if (l0 < vl) {  // skip load entirely past valid prefix
        int4 xv = ((const int4*)(X + b * LL))[tid];
        atomicAdd(&whist[warp][xv.x], 1);
        if (l0 + 1 < vl) atomicAdd(&whist[warp][xv.y], 1);
        if (l0 + 2 < vl) atomicAdd(&whist[warp][xv.z], 1);
        if (l0 + 3 < vl) atomicAdd(&whist[warp][xv.w], 1);
    }
    __syncthreads();

    // ---- reduce histograms -> float counts (padded to 36) ----
    if (tid < 36) {
        float s = 0.0f;
        if (tid < VOCAB) {
            int a = 0;
            #pragma unroll
            for (int w = 0; w < NWARP; w++) a += whist[w][tid];
            s = (float)a;
        }
        cnt[tid] = s;
    }
    __syncthreads();

    // ---- pooled[d] = sum_v cnt[v]*emb[v][d], split across 4 vocab groups ----
    {
        const int g4 = tid >> 8;      // 0..3
        const int d  = tid & 255;
        float acc = 0.0f;
        #pragma unroll
        for (int j = 0; j < 9; j++) {
            const int v = g4 * 9 + j; // 0..35
            if (v < VOCAB)
                acc = fmaf(cnt[v], emb[v * DD + d], acc);
        }
        part[g4][d] = acc;
    }
    __syncthreads();
    if (tid < DD)
        vecA[tid] = part[0][tid] + part[1][tid] + part[2][tid] + part[3][tid];
    __syncthreads();

    const int g    = tid >> 6;   // split-K group: 0..15
    const int lane = tid & 63;   // output float4 index
    const int k0   = g * KPG;

    // ---- layer 1: h = relu(pooled @ W1 + b1) ----
    {
        const float4* W1v = (const float4*)W1;
        float4 acc = make_float4(0.f, 0.f, 0.f, 0.f);
        #pragma unroll
        for (int kk = 0; kk < KPG; kk++) {
            const int k = k0 + kk;
            const float  s = vecA[k];
            const float4 w = W1v[k * (DD / 4) + lane];
            acc.x = fmaf(s, w.x, acc.x);
            acc.y = fmaf(s, w.y, acc.y);
            acc.z = fmaf(s, w.z, acc.z);
            acc.w = fmaf(s, w.w, acc.w);
        }
        ((float4*)part[g])[lane] = acc;
        __syncthreads();   // vecA reads done; partials visible

        if (tid < DD) {
            float h = b1[tid];
            #pragma unroll
            for (int r = 0; r < KG; r++) h += part[r][tid];
            vecA[tid] = fmaxf(h, 0.0f);   // WAR on vecA covered by sync above
        }
        __syncthreads();   // new vecA visible; part reads done before reuse
    }

    // ---- layer 2: out = relu(h @ W2 + b2) ----
    {
        const float4* W2v = (const float4*)W2;
        float4 acc = make_float4(0.f, 0.f, 0.f, 0.f);
        #pragma unroll
        for (int kk = 0; kk < KPG; kk++) {
            const int k = k0 + kk;
            const float  s = vecA[k];
            const float4 w = W2v[k * (DD / 4) + lane];
            acc.x = fmaf(s, w.x, acc.x);
            acc.y = fmaf(s, w.y, acc.y);
            acc.z = fmaf(s, w.z, acc.z);
            acc.w = fmaf(s, w.w, acc.w);
        }
        ((float4*)part[g])[lane] = acc;
        __syncthreads();

        if (tid < DD) {
            float o = b2[tid];
            #pragma unroll
            for (int r = 0; r < KG; r++) o += part[r][tid];
            out[b * DD + tid] = fmaxf(o, 0.0f);
        }
    }
}

extern "C" void kernel_launch(void* const* d_in, const int* in_sizes, int n_in,
                              void* d_out, int out_size)
{
    const int*   X    = (const int*)d_in[0];
    const int*   vlen = (const int*)d_in[1];
    const float* emb  = (const float*)d_in[2];
    const float* W1   = (const float*)d_in[3];
    const float* b1   = (const float*)d_in[4];
    const float* W2   = (const float*)d_in[5];
    const float* b2   = (const float*)d_in[6];
    float*       out  = (float*)d_out;

    prot_net_fused_kernel<<<BB, NT>>>(X, vlen, emb, W1, b1, W2, b2, out);
}